// round 9
// baseline (speedup 1.0000x reference)
#include <cuda_runtime.h>
#include <cuda_bf16.h>

// BPMLL loss — single-wave grid, fused winner tail, one graph node.
//   128 blocks x 512 threads (one block per SM, single wave); 4 rows/block,
//   128 threads/row, 4 elems/thread (one float4+int4).
//   Row reduce: ballot+popc for counts, two interleaved shfl_xor butterflies
//   for pos/neg. Block leader (tid 0) combines 4 rows, fires ONE
//   red.global.add.f32 into g_acc, bumps an acq_rel counter; the last block
//   reads+resets g_acc with a single atom.exch (one L2 round trip) and
//   writes out. g_count reset by plain store (next replay ordered by kernel
//   boundary).
//
// Math per element (2 MUFU + 4 FMA):
//   exp(-sigmoid(c)) = e^{-1} * exp(sigmoid(-c)) -> h(x)=exp(sigmoid(x)),
//   x = y ? -c : c. sigmoid = EX2+RCP; exp(s), s in (0,1), degree-4 poly.

#define ROWS 512
#define COLS 512
#define NBLK 128
#define TPB  512
#define ROWS_PER_BLK 4

#define D0 1.00002694f
#define D1 0.99871530f
#define D2 0.50996560f
#define D3 0.13998530f
#define D4 0.06956140f
#define E_INV_OVER_ROWS (0.36787944117144233f / 512.0f)

__device__ float        g_acc   = 0.0f;
__device__ unsigned int g_count = 0;

__device__ __forceinline__ void elem(float c, int y, float& pos, float& neg) {
    float x = __int_as_float(__float_as_int(c) ^ (y << 31));  // y ? -c : c
    float t = __expf(-x);                                     // MUFU.EX2
    float s;
    asm("rcp.approx.f32 %0, %1;" : "=f"(s) : "f"(1.0f + t));  // MUFU.RCP
    float h = fmaf(s, D4, D3);
    h = fmaf(h, s, D2);
    h = fmaf(h, s, D1);
    h = fmaf(h, s, D0);
    if (y) pos += h; else neg += h;
}

__global__ __launch_bounds__(TPB) void bpmll_kernel(const float* __restrict__ c,
                                                    const int*   __restrict__ y,
                                                    float* __restrict__ out) {
    const int tid    = threadIdx.x;
    const int lane   = tid & 31;
    const int warp   = tid >> 5;            // 0..15
    const int rsub   = tid >> 7;            // 0..3: row within block
    const int tid128 = tid & 127;
    const int row    = blockIdx.x * ROWS_PER_BLK + rsub;

    const float4 cv = reinterpret_cast<const float4*>(c)[(size_t)row * (COLS / 4) + tid128];
    const int4   yv = reinterpret_cast<const int4*>(y)[(size_t)row * (COLS / 4) + tid128];

    float pos = 0.0f, neg = 0.0f;
    elem(cv.x, yv.x, pos, neg);
    elem(cv.y, yv.y, pos, neg);
    elem(cv.z, yv.z, pos, neg);
    elem(cv.w, yv.w, pos, neg);

    // Label count: 4 ballots + popc (no shuffle chain).
    int ys = __popc(__ballot_sync(0xFFFFFFFFu, yv.x))
           + __popc(__ballot_sync(0xFFFFFFFFu, yv.y))
           + __popc(__ballot_sync(0xFFFFFFFFu, yv.z))
           + __popc(__ballot_sync(0xFFFFFFFFu, yv.w));

    // Two interleaved butterfly chains — latency overlaps.
    #pragma unroll
    for (int o = 16; o > 0; o >>= 1) {
        pos += __shfl_xor_sync(0xFFFFFFFFu, pos, o);
        neg += __shfl_xor_sync(0xFFFFFFFFu, neg, o);
    }

    __shared__ float sp[16];
    __shared__ float sn[16];
    __shared__ int   si[16];
    if (lane == 0) { sp[warp] = pos; sn[warp] = neg; si[warp] = ys; }
    __syncthreads();

    if (tid == 0) {
        float part = 0.0f;
        #pragma unroll
        for (int r = 0; r < ROWS_PER_BLK; r++) {
            const int b = r * 4;
            float P = (sp[b] + sp[b + 1]) + (sp[b + 2] + sp[b + 3]);
            float N = (sn[b] + sn[b + 1]) + (sn[b + 2] + sn[b + 3]);
            int   Y = (si[b] + si[b + 1]) + (si[b + 2] + si[b + 3]);
            part += __fdividef(P * N * E_INV_OVER_ROWS,
                               (float)Y * (float)(COLS - Y));
        }
        // Fire-and-forget accumulate (pipelined single-address REDG).
        asm volatile("red.global.add.f32 [%0], %1;"
                     :: "l"(&g_acc), "f"(part) : "memory");
        // Release: orders the RED above before the counter bump.
        unsigned int old;
        asm volatile("atom.acq_rel.gpu.global.add.u32 %0, [%1], %2;"
                     : "=r"(old) : "l"(&g_count), "r"(1u) : "memory");
        if (old == (unsigned)(NBLK - 1)) {
            // Fused read+reset: one L2 round trip returns total and zeroes g_acc.
            unsigned int tb;
            asm volatile("atom.acq_rel.gpu.global.exch.b32 %0, [%1], %2;"
                         : "=r"(tb) : "l"(&g_acc), "r"(0u) : "memory");
            out[0] = __uint_as_float(tb);
            asm volatile("st.global.cg.u32 [%0], %1;"
                         :: "l"(&g_count), "r"(0u) : "memory");
        }
    }
}

extern "C" void kernel_launch(void* const* d_in, const int* in_sizes, int n_in,
                              void* d_out, int out_size) {
    const float* c = (const float*)d_in[0];
    const int*   y = (const int*)d_in[1];
    float*       out = (float*)d_out;
    bpmll_kernel<<<NBLK, TPB>>>(c, y, out);
}

// round 10
// speedup vs baseline: 1.2804x; 1.2804x over previous
#include <cuda_runtime.h>
#include <cuda_bf16.h>

// BPMLL loss — single graph node, single-round-trip tail.
//   256 blocks x 256 threads; 128 threads/row (2 rows/block), 4 elems/thread.
//   Tail: ONE atom.add.u64 per block into g_pack, packing
//     bits [52..60): arrival count (+1 per block)
//     bits [0..52):  fixed-point sum (scale 2^44) of the block's partial
//   The leader whose returned count == NBLK-1 already holds the grand total
//   (old + own addend): no second atomic, no counter, no fence. It converts,
//   stores out[0], and resets g_pack for graph replay. Integer accumulation
//   is bit-deterministic.
//
// Math per element (2 MUFU + 4 FMA):
//   exp(-sigmoid(c)) = e^{-1} * exp(sigmoid(-c)) -> h(x)=exp(sigmoid(x)),
//   x = y ? -c : c. sigmoid = EX2+RCP; exp(s), s in (0,1), degree-4 poly.
//   Bound: per-row partial <= e/512, total <= e  -> fits bits [0,46) @2^44.

#define ROWS 512
#define COLS 512
#define NBLK 256
#define TPB  256

#define D0 1.00002694f
#define D1 0.99871530f
#define D2 0.50996560f
#define D3 0.13998530f
#define D4 0.06956140f
#define E_INV_OVER_ROWS (0.36787944117144233f / 512.0f)

#define CNT_ONE   (1ULL << 52)
#define SUM_MASK  ((1ULL << 52) - 1ULL)
#define FIX_SCALE 0x1p44f
#define FIX_INV   0x1p-44f

__device__ unsigned long long g_pack = 0ULL;

__device__ __forceinline__ void elem(float c, int y, float& pos, float& neg) {
    float x = __int_as_float(__float_as_int(c) ^ (y << 31));  // y ? -c : c
    float t = __expf(-x);                                     // MUFU.EX2
    float s;
    asm("rcp.approx.f32 %0, %1;" : "=f"(s) : "f"(1.0f + t));  // MUFU.RCP
    float h = fmaf(s, D4, D3);
    h = fmaf(h, s, D2);
    h = fmaf(h, s, D1);
    h = fmaf(h, s, D0);
    if (y) pos += h; else neg += h;
}

__global__ __launch_bounds__(TPB) void bpmll_kernel(const float* __restrict__ c,
                                                    const int*   __restrict__ y,
                                                    float* __restrict__ out) {
    const int tid    = threadIdx.x;
    const int lane   = tid & 31;
    const int warp   = tid >> 5;          // 0..7
    const int rhalf  = tid >> 7;          // 0/1: row within block
    const int tid128 = tid & 127;
    const int row    = blockIdx.x * 2 + rhalf;

    const float4 cv = reinterpret_cast<const float4*>(c)[(size_t)row * (COLS / 4) + tid128];
    const int4   yv = reinterpret_cast<const int4*>(y)[(size_t)row * (COLS / 4) + tid128];

    float pos = 0.0f, neg = 0.0f;
    elem(cv.x, yv.x, pos, neg);
    elem(cv.y, yv.y, pos, neg);
    elem(cv.z, yv.z, pos, neg);
    elem(cv.w, yv.w, pos, neg);

    // Label count: 4 ballots + popc (no shuffle chain).
    int ys = __popc(__ballot_sync(0xFFFFFFFFu, yv.x))
           + __popc(__ballot_sync(0xFFFFFFFFu, yv.y))
           + __popc(__ballot_sync(0xFFFFFFFFu, yv.z))
           + __popc(__ballot_sync(0xFFFFFFFFu, yv.w));

    // Two interleaved butterfly chains — latency overlaps.
    #pragma unroll
    for (int o = 16; o > 0; o >>= 1) {
        pos += __shfl_xor_sync(0xFFFFFFFFu, pos, o);
        neg += __shfl_xor_sync(0xFFFFFFFFu, neg, o);
    }

    __shared__ float sp[8];
    __shared__ float sn[8];
    __shared__ int   si[8];
    if (lane == 0) { sp[warp] = pos; sn[warp] = neg; si[warp] = ys; }
    __syncthreads();

    if (tid == 0) {
        float P0 = (sp[0] + sp[1]) + (sp[2] + sp[3]);
        float N0 = (sn[0] + sn[1]) + (sn[2] + sn[3]);
        int   Y0 = (si[0] + si[1]) + (si[2] + si[3]);
        float P1 = (sp[4] + sp[5]) + (sp[6] + sp[7]);
        float N1 = (sn[4] + sn[5]) + (sn[6] + sn[7]);
        int   Y1 = (si[4] + si[5]) + (si[6] + si[7]);
        float part = __fdividef(P0 * N0 * E_INV_OVER_ROWS,
                                (float)Y0 * (float)(COLS - Y0))
                   + __fdividef(P1 * N1 * E_INV_OVER_ROWS,
                                (float)Y1 * (float)(COLS - Y1));

        // Pack: count in bits [52..), fixed-point sum (scale 2^44) below.
        unsigned long long add = CNT_ONE + __float2ull_rn(part * FIX_SCALE);
        unsigned long long old;
        asm volatile("atom.global.add.u64 %0, [%1], %2;"
                     : "=l"(old) : "l"(&g_pack), "l"(add) : "memory");

        if ((old >> 52) == (unsigned long long)(NBLK - 1)) {
            // This atomic was the last: old + add IS the grand total.
            unsigned long long total_fix = (old + add) & SUM_MASK;
            out[0] = (float)((double)total_fix) * FIX_INV;
            // Reset for next graph replay (all NBLK atomics already applied;
            // next launch ordered by kernel boundary).
            asm volatile("st.global.cg.u64 [%0], %1;"
                         :: "l"(&g_pack), "l"(0ULL) : "memory");
        }
    }
}

extern "C" void kernel_launch(void* const* d_in, const int* in_sizes, int n_in,
                              void* d_out, int out_size) {
    const float* c = (const float*)d_in[0];
    const int*   y = (const int*)d_in[1];
    float*       out = (float*)d_out;
    bpmll_kernel<<<NBLK, TPB>>>(c, y, out);
}

// round 11
// speedup vs baseline: 1.3632x; 1.0647x over previous
#include <cuda_runtime.h>
#include <cuda_bf16.h>

// BPMLL loss — single graph node, packed-atomic tail, integer-redux reductions.
//   256 blocks x 256 threads; 128 threads/row (2 rows/block), 4 elems/thread.
//   Warp reduce: pos/neg converted to fixed-point u32 (scale 2^20, exact since
//   values < 2^24) and reduced with single-instruction redux.sync.add.u32
//   (replaces two 5-level SHFL butterflies, ~130 cyc). Counts via ballot+popc.
//   Tail: ONE atom.add.u64 packing {count:bits>=52, fixed-sum(2^44):bits<52};
//   the block seeing count==NBLK-1 holds the grand total in old+add — zero
//   extra round trips. It writes out[0] and resets g_pack for graph replay.
//
// Math per element (2 MUFU + 4 FMA):
//   exp(-sigmoid(c)) = e^{-1} * exp(sigmoid(-c)) -> h(x)=exp(sigmoid(x)),
//   x = y ? -c : c. sigmoid = EX2+RCP; exp(s), s in (0,1), degree-4 poly.

#define ROWS 512
#define COLS 512
#define NBLK 256
#define TPB  256

#define D0 1.00002694f
#define D1 0.99871530f
#define D2 0.50996560f
#define D3 0.13998530f
#define D4 0.06956140f
#define E_INV_OVER_ROWS (0.36787944117144233f / 512.0f)

#define WSCALE  0x1p20f     // per-thread fixed-point scale for pos/neg
#define WINV    0x1p-20f

#define CNT_ONE   (1ULL << 52)
#define SUM_MASK  ((1ULL << 52) - 1ULL)
#define FIX_SCALE 0x1p44f
#define FIX_INV   0x1p-44f

__device__ unsigned long long g_pack = 0ULL;

__device__ __forceinline__ void elem(float c, int y, float& pos, float& neg) {
    float x = __int_as_float(__float_as_int(c) ^ (y << 31));  // y ? -c : c
    float t = __expf(-x);                                     // MUFU.EX2
    float s;
    asm("rcp.approx.f32 %0, %1;" : "=f"(s) : "f"(1.0f + t));  // MUFU.RCP
    float h = fmaf(s, D4, D3);
    h = fmaf(h, s, D2);
    h = fmaf(h, s, D1);
    h = fmaf(h, s, D0);
    if (y) pos += h; else neg += h;
}

__global__ __launch_bounds__(TPB) void bpmll_kernel(const float* __restrict__ c,
                                                    const int*   __restrict__ y,
                                                    float* __restrict__ out) {
    const int tid    = threadIdx.x;
    const int lane   = tid & 31;
    const int warp   = tid >> 5;          // 0..7
    const int tid128 = tid & 127;
    const int row    = blockIdx.x * 2 + (tid >> 7);

    const float4 cv = reinterpret_cast<const float4*>(c)[(size_t)row * (COLS / 4) + tid128];
    const int4   yv = reinterpret_cast<const int4*>(y)[(size_t)row * (COLS / 4) + tid128];

    float pos = 0.0f, neg = 0.0f;
    elem(cv.x, yv.x, pos, neg);
    elem(cv.y, yv.y, pos, neg);
    elem(cv.z, yv.z, pos, neg);
    elem(cv.w, yv.w, pos, neg);

    // Label count: 4 ballots + popc.
    int ys = __popc(__ballot_sync(0xFFFFFFFFu, yv.x))
           + __popc(__ballot_sync(0xFFFFFFFFu, yv.y))
           + __popc(__ballot_sync(0xFFFFFFFFu, yv.z))
           + __popc(__ballot_sync(0xFFFFFFFFu, yv.w));

    // Fixed-point warp reduction: single-instruction integer redux (sm_80+).
    // pos,neg < 4e ~ 10.9 -> *2^20 < 2^24 (exact in f32, exact F2I).
    unsigned int up = __float2uint_rn(pos * WSCALE);
    unsigned int un = __float2uint_rn(neg * WSCALE);
    unsigned int upw = __reduce_add_sync(0xFFFFFFFFu, up);   // REDUX.SUM
    unsigned int unw = __reduce_add_sync(0xFFFFFFFFu, un);

    __shared__ unsigned int su[8];
    __shared__ unsigned int sv[8];
    __shared__ int          si[8];
    if (lane == 0) { su[warp] = upw; sv[warp] = unw; si[warp] = ys; }
    __syncthreads();

    if (tid == 0) {
        // Row 0 = warps 0-3, row 1 = warps 4-7 (integer sums fit: <2^31).
        unsigned int P0i = (su[0] + su[1]) + (su[2] + su[3]);
        unsigned int N0i = (sv[0] + sv[1]) + (sv[2] + sv[3]);
        int          Y0  = (si[0] + si[1]) + (si[2] + si[3]);
        unsigned int P1i = (su[4] + su[5]) + (su[6] + su[7]);
        unsigned int N1i = (sv[4] + sv[5]) + (sv[6] + sv[7]);
        int          Y1  = (si[4] + si[5]) + (si[6] + si[7]);
        float P0 = (float)P0i * WINV, N0 = (float)N0i * WINV;
        float P1 = (float)P1i * WINV, N1 = (float)N1i * WINV;
        float part = __fdividef(P0 * N0 * E_INV_OVER_ROWS,
                                (float)Y0 * (float)(COLS - Y0))
                   + __fdividef(P1 * N1 * E_INV_OVER_ROWS,
                                (float)Y1 * (float)(COLS - Y1));

        // Packed count+sum atomic: one L2 round trip finishes everything.
        unsigned long long add = CNT_ONE + __float2ull_rn(part * FIX_SCALE);
        unsigned long long old;
        asm volatile("atom.global.add.u64 %0, [%1], %2;"
                     : "=l"(old) : "l"(&g_pack), "l"(add) : "memory");

        if ((old >> 52) == (unsigned long long)(NBLK - 1)) {
            unsigned long long total_fix = (old + add) & SUM_MASK;
            out[0] = (float)((double)total_fix) * FIX_INV;
            asm volatile("st.global.cg.u64 [%0], %1;"
                         :: "l"(&g_pack), "l"(0ULL) : "memory");
        }
    }
}

extern "C" void kernel_launch(void* const* d_in, const int* in_sizes, int n_in,
                              void* d_out, int out_size) {
    const float* c = (const float*)d_in[0];
    const int*   y = (const int*)d_in[1];
    float*       out = (float*)d_out;
    bpmll_kernel<<<NBLK, TPB>>>(c, y, out);
}